// round 15
// baseline (speedup 1.0000x reference)
#include <cuda_runtime.h>
#include <cuda.h>
#include <cuda_fp16.h>
#include <cstdint>
#include <math.h>

#define BATCH 64
#define NPTS 2048
#define KDIM 98304            // 2048*48
#define NCLS 1000
#define NPAD 1024
#define KSPLITS 64
#define KSP (KDIM / KSPLITS)  // 1536
#define KB 32                 // K per stage
#define STAGES_PER_CTA (KSP / KB)  // 48
#define TN 256
#define NSTAGES 3
#define RGROUPS 4
#define SPG (KSPLITS / RGROUPS)   // 16

#define B_SLAB 4096                          // 32 k-rows x 128B (fp32, SW128)
#define B_BYTES (8 * B_SLAB)                 // 32768
#define A_SLOT 1056                          // 64 rows x 16B + 32B pad
#define A_BYTES (4 * A_SLOT)                 // 4224
#define STAGE_BYTES 37888                    // 37*1024
#define SMEM_DYN (NSTAGES * STAGE_BYTES + 1024)   // 114688 -> 2 CTAs/SM

// ------------------------- device scratch -------------------------
__device__ float g_tv[BATCH * 48];
__device__ float g_xy[BATCH * NPTS * 2];
__device__ __align__(16) __half g_Ph[(size_t)BATCH * KDIM];  // fp16, k-permuted
__device__ float g_part[(size_t)KSPLITS * BATCH * NPAD];     // 16 MB
__device__ float g_part2[(size_t)RGROUPS * BATCH * NPAD];    // 1 MB

// ------------------------- helpers -------------------------
__device__ __forceinline__ uint32_t smem_u32(const void* p) {
    uint32_t a;
    asm("{ .reg .u64 t; cvta.to.shared.u64 t, %1; cvt.u32.u64 %0, t; }" : "=r"(a) : "l"(p));
    return a;
}
__device__ __forceinline__ void cp_async16(uint32_t dst, const void* src) {
    asm volatile("cp.async.cg.shared.global [%0], [%1], 16;" :: "r"(dst), "l"(src) : "memory");
}
__device__ __forceinline__ void cp_commit() { asm volatile("cp.async.commit_group;" ::: "memory"); }
__device__ __forceinline__ void cp_wait1()  { asm volatile("cp.async.wait_group 1;" ::: "memory"); }
#define MBAR_INIT(addr, cnt) \
    asm volatile("mbarrier.init.shared.b64 [%0], %1;" :: "r"(addr), "r"(cnt) : "memory")
#define MBAR_EXPECT_TX(addr, bytes) \
    asm volatile("mbarrier.arrive.expect_tx.shared.b64 _, [%0], %1;" :: "r"(addr), "r"(bytes) : "memory")
#define MBAR_WAIT(addr, parity) do { \
    uint32_t _m = (addr), _p = (parity), _d; \
    asm volatile("{\n\t.reg .pred p;\n\tmbarrier.try_wait.parity.acquire.cta.shared::cta.b64 p, [%1], %2;\n\tselp.b32 %0,1,0,p;\n\t}" \
        : "=r"(_d) : "r"(_m), "r"(_p) : "memory"); \
    if (!_d) { \
        asm volatile("{\n\t.reg .pred P1;\n\tWL_%=:\n\tmbarrier.try_wait.parity.acquire.cta.shared::cta.b64 P1, [%0], %1, 0x989680;\n\t@P1 bra.uni WD_%=;\n\tbra.uni WL_%=;\n\tWD_%=:\n\t}" \
            :: "r"(_m), "r"(_p) : "memory"); \
    } \
} while (0)
#define TMA_LOAD_2D(smem, map, cx, cy, mbar) \
    asm volatile("cp.async.bulk.tensor.2d.shared::cta.global.tile.mbarrier::complete_tx::bytes [%0], [%1, {%2, %3}], [%4];" \
        :: "r"(smem), "l"(map), "r"(cx), "r"(cy), "r"(mbar) : "memory")

__device__ __forceinline__ uint32_t pack_f16x2(float lo, float hi) {
    uint32_t r;
    asm("cvt.rn.f16x2.f32 %0, %1, %2;" : "=r"(r) : "f"(hi), "f"(lo));
    return r;
}
__device__ __forceinline__ void mma_f16(float* c, uint32_t a0, uint32_t a1, uint32_t a2,
                                        uint32_t a3, uint32_t b0, uint32_t b1) {
    asm volatile(
        "mma.sync.aligned.m16n8k16.row.col.f32.f16.f16.f32 "
        "{%0,%1,%2,%3}, {%4,%5,%6,%7}, {%8,%9}, {%0,%1,%2,%3};"
        : "+f"(c[0]), "+f"(c[1]), "+f"(c[2]), "+f"(c[3])
        : "r"(a0), "r"(a1), "r"(a2), "r"(a3), "r"(b0), "r"(b1));
}

// ---------------------------------------------------------------------------
// Kernel 1a: tv resize. 64 blocks x 48 threads.
// ---------------------------------------------------------------------------
__global__ void k_tv(const float* __restrict__ tv_img) {
    int b = blockIdx.x, d = threadIdx.x;
    int c = d / 16, rem = d % 16, i = rem / 4, j = rem % 4;
    const float* base = tv_img + ((size_t)(b * 3 + c)) * 64 * 64;
    int r0 = 16 * i + 7, c0 = 16 * j + 7;
    g_tv[b * 48 + d] = 0.25f * (base[r0 * 64 + c0] + base[r0 * 64 + c0 + 1] +
                                base[(r0 + 1) * 64 + c0] + base[(r0 + 1) * 64 + c0 + 1]);
}

// ---------------------------------------------------------------------------
// Kernel 1b: coords. 16 CTAs x 256 thr.
// ---------------------------------------------------------------------------
__global__ void __launch_bounds__(256) k_coords2(const float* __restrict__ w1,
                                                 const float* __restrict__ b1) {
    __shared__ float tv_s[BATCH * 48];
    int tid = threadIdx.x;
    int m = blockIdx.x * 256 + tid;
#pragma unroll
    for (int i = 0; i < 12; i++)
        tv_s[tid + i * 256] = g_tv[tid + i * 256];
    __syncthreads();

    float wcol[48];
#pragma unroll
    for (int d = 0; d < 48; d++) wcol[d] = w1[d * 4096 + m];
    float bias = b1[m];
    int p = m >> 1, q = m & 1;

    for (int b = 0; b < BATCH; b++) {
        const float* tvb = &tv_s[b * 48];
        float acc = bias;
#pragma unroll
        for (int d = 0; d < 48; d++) acc += wcol[d] * tvb[d];
        float s = 1.0f / (1.0f + expf(-acc));
        g_xy[(b * NPTS + p) * 2 + q] = s * 1019.0f + 2.0f;
    }
}

// ---------------------------------------------------------------------------
// Kernel 2: gather, division-free, SMEM-staged output (coalesced float4 STG).
// ---------------------------------------------------------------------------
#define GPTS 16
__global__ void __launch_bounds__(256) k_gather(const float* __restrict__ img) {
    __shared__ float px[GPTS][5][16];
    __shared__ float sfx[GPTS], sfy[GPTS];
    __shared__ int   sbase[GPTS];
    __shared__ __align__(16) __half sh_out[GPTS * 48];

    const int tid = threadIdx.x;
    const int g = tid >> 4;
    const int f = tid & 15;
    const int b  = blockIdx.x >> 7;
    const int p0 = (blockIdx.x & 127) << 4;

    if (tid < GPTS) {
        int p = p0 + tid;
        float2 xy = *(const float2*)&g_xy[(b * NPTS + p) * 2];
        float x0 = floorf(xy.x), y0 = floorf(xy.y);
        sfx[tid] = xy.x - x0;
        sfy[tid] = xy.y - y0;
        sbase[tid] = (((int)x0 - 2) << 10) * 3 + ((int)y0 - 2) * 3;
    }
    __syncthreads();

    const float* ib = img + (size_t)b * (1024u * 1024u * 3u);
    if (f < 15) {
        const float* src = ib + sbase[g] + f;
#pragma unroll
        for (int row = 0; row < 5; row++)
            px[g][row][f] = src[row * 3072];
    }
    __syncthreads();

    const int i = f >> 2, j = f & 3;
    float fx = sfx[g], fy = sfy[g];
    float w00 = (1.0f - fx) * (1.0f - fy);
    float w01 = (1.0f - fx) * fy;
    float w10 = fx * (1.0f - fy);
    float w11 = fx * fy;

    const float* r0 = &px[g][i][j * 3];
    const float* r1 = &px[g][i + 1][j * 3];

    int kloc = g * 48 + f * 3;
#pragma unroll
    for (int ch = 0; ch < 3; ch++) {
        float v = r0[ch] * w00 + r0[ch + 3] * w01 + r1[ch] * w10 + r1[ch + 3] * w11;
        int k = kloc + ch;
        int off = k & 31;
        int r = off & 15, kb = off >> 4;
        int t = (r >> 1) & 3, pair = r >> 3, elem = r & 1;
        int pos = (t << 3) | (kb << 2) | (pair << 1) | elem;
        sh_out[(k & ~31) | pos] = __float2half_rn(v);
    }
    __syncthreads();

    if (tid < 96) {
        float4 v4 = *(const float4*)&sh_out[tid * 8];
        *(float4*)&g_Ph[(size_t)b * KDIM + p0 * 48 + tid * 8] = v4;
    }
}

// ---------------------------------------------------------------------------
// Kernel 3: fp16 mma.sync m16n8k16 split-K GEMM.
// TN=256, 2 CTAs/SM, grid (4, 64) = 256 CTAs single wave, 3-stage pipeline,
// ONE __syncthreads per stage. Warp tile m64 x n32. (R13 shape + R14 sync.)
// ---------------------------------------------------------------------------
__global__ void __launch_bounds__(256, 2) k_gemm(const __grid_constant__ CUtensorMap tmB) {
    extern __shared__ __align__(16) char smem_raw[];
    __shared__ __align__(16) uint64_t mbar[NSTAGES];

    const int tid = threadIdx.x;
    const int wid = tid >> 5;
    const int lane = tid & 31;
    const int n0 = blockIdx.x * TN;
    const int ksplit = blockIdx.y;
    const int k0 = ksplit * KSP;
    const int g  = lane >> 2;
    const int t  = lane & 3;

    const uint32_t sbase = (smem_u32(smem_raw) + 1023u) & ~1023u;
    const uint32_t mb = smem_u32(mbar);

    if (tid == 0) {
#pragma unroll
        for (int s = 0; s < NSTAGES; s++) MBAR_INIT(mb + s * 8, 1);
    }
    __syncthreads();

    auto issue_A = [&](int slot, int kofs) {
        uint32_t st = sbase + slot * STAGE_BYTES + B_BYTES;
        int row = tid & 63, c = tid >> 6;
        cp_async16(st + c * A_SLOT + row * 16,
                   &g_Ph[(size_t)row * KDIM + kofs + c * 8]);
        cp_commit();
    };
    auto issue_B = [&](int slot, int kofs) {
        if (tid == 0) {
            uint32_t full = mb + slot * 8;
            uint32_t bdst = sbase + slot * STAGE_BYTES;
            MBAR_EXPECT_TX(full, B_BYTES);
#pragma unroll
            for (int j = 0; j < 8; j++)
                TMA_LOAD_2D(bdst + j * B_SLAB, &tmB, n0 + 32 * j, kofs, full);
        }
    };

    // prologue: stages 0 and 1
    issue_B(0, k0);           issue_A(0, k0);
    issue_B(1, k0 + KB);      issue_A(1, k0 + KB);

    float acc[16][4];
#pragma unroll
    for (int j = 0; j < 16; j++)
#pragma unroll
        for (int r = 0; r < 4; r++) acc[j][r] = 0.0f;

    uint32_t col0[4], col1[4];
#pragma unroll
    for (int nt = 0; nt < 4; nt++) {
        uint32_t n = nt * 8 + g;
        uint32_t chunk = n >> 2, e = (n & 3) * 4;
        col0[nt] = ((chunk ^ (uint32_t)(2 * t)) << 4) + e;
        col1[nt] = ((chunk ^ (uint32_t)(2 * t + 1)) << 4) + e;
    }

    int slot = 0, phase = 0;
    int pslot = 2;
    for (int s = 0; s < STAGES_PER_CTA; s++) {
        cp_wait1();                        // A(s) done (A(s+1) outstanding)
        MBAR_WAIT(mb + slot * 8, phase);   // B(s) done
        __syncthreads();                   // all warps done consuming stage s-1

        int sn = s + 2;
        if (sn < STAGES_PER_CTA) {         // slot (s+2)%3 consumed at iter s-1: safe
            issue_B(pslot, k0 + sn * KB);
            issue_A(pslot, k0 + sn * KB);
        } else cp_commit();
        if (++pslot == NSTAGES) pslot = 0;

        uint32_t st = sbase + slot * STAGE_BYTES;
        uint32_t abase = st + B_BYTES + t * A_SLOT;
        uint32_t bslab = st + wid * B_SLAB;

        uint4 av[8];
#pragma unroll
        for (int jr = 0; jr < 8; jr++) {
            asm volatile("ld.shared.v4.u32 {%0,%1,%2,%3}, [%4];"
                : "=r"(av[jr].x), "=r"(av[jr].y), "=r"(av[jr].z), "=r"(av[jr].w)
                : "r"(abase + (jr * 8 + g) * 16));
        }

#pragma unroll
        for (int kb = 0; kb < 2; kb++) {
            uint32_t rb0 = bslab + (kb * 16 + 2 * t) * 128;
            uint32_t rb1 = rb0 + 128;
#pragma unroll
            for (int nt = 0; nt < 4; nt++) {
                float v00, v01, v10, v11;
                asm volatile("ld.shared.f32 %0, [%1];" : "=f"(v00) : "r"(rb0 + col0[nt]));
                asm volatile("ld.shared.f32 %0, [%1];" : "=f"(v01) : "r"(rb1 + col1[nt]));
                asm volatile("ld.shared.f32 %0, [%1];" : "=f"(v10) : "r"(rb0 + 1024 + col0[nt]));
                asm volatile("ld.shared.f32 %0, [%1];" : "=f"(v11) : "r"(rb1 + 1024 + col1[nt]));
                uint32_t b0 = pack_f16x2(v00, v01);
                uint32_t b1 = pack_f16x2(v10, v11);
#pragma unroll
                for (int mt = 0; mt < 4; mt++) {
                    uint32_t a0 = kb ? av[2 * mt].z     : av[2 * mt].x;
                    uint32_t a2 = kb ? av[2 * mt].w     : av[2 * mt].y;
                    uint32_t a1 = kb ? av[2 * mt + 1].z : av[2 * mt + 1].x;
                    uint32_t a3 = kb ? av[2 * mt + 1].w : av[2 * mt + 1].y;
                    mma_f16(acc[mt * 4 + nt], a0, a1, a2, a3, b0, b1);
                }
            }
        }
        if (++slot == NSTAGES) { slot = 0; phase ^= 1; }
    }

    float* base = &g_part[(size_t)ksplit * BATCH * NPAD];
#pragma unroll
    for (int mt = 0; mt < 4; mt++) {
#pragma unroll
        for (int nt = 0; nt < 4; nt++) {
            int m = mt * 16 + g;
            int n = n0 + wid * 32 + nt * 8 + 2 * t;
            float* a = acc[mt * 4 + nt];
            *(float2*)&base[(size_t)m * NPAD + n] = make_float2(a[0], a[1]);
            *(float2*)&base[(size_t)(m + 8) * NPAD + n] = make_float2(a[2], a[3]);
        }
    }
}

// ---------------------------------------------------------------------------
// Kernel 4a: reduce phase 1 — each (output, group) sums SPG splits
// ---------------------------------------------------------------------------
__global__ void k_reduce1() {
    int idx = blockIdx.x * blockDim.x + threadIdx.x;
    if (idx >= BATCH * NCLS) return;
    int grp = blockIdx.y;
    int b = idx / NCLS, n = idx % NCLS;
    float acc = 0.0f;
#pragma unroll
    for (int s = 0; s < SPG; s++)
        acc += g_part[((size_t)(grp * SPG + s) * BATCH + b) * NPAD + n];
    g_part2[((size_t)grp * BATCH + b) * NPAD + n] = acc;
}

// ---------------------------------------------------------------------------
// Kernel 4b: reduce phase 2 — sum RGROUPS + bias -> out
// ---------------------------------------------------------------------------
__global__ void k_reduce2(float* __restrict__ out, const float* __restrict__ b2) {
    int idx = blockIdx.x * blockDim.x + threadIdx.x;
    if (idx >= BATCH * NCLS) return;
    int b = idx / NCLS, n = idx % NCLS;
    float acc = b2[n];
#pragma unroll
    for (int g = 0; g < RGROUPS; g++)
        acc += g_part2[((size_t)g * BATCH + b) * NPAD + n];
    out[idx] = acc;
}

// ---------------------------------------------------------------------------
typedef CUresult (*PFN_encode_t)(CUtensorMap*, CUtensorMapDataType, cuuint32_t, void*,
                                 const cuuint64_t*, const cuuint64_t*, const cuuint32_t*,
                                 const cuuint32_t*, CUtensorMapInterleave, CUtensorMapSwizzle,
                                 CUtensorMapL2promotion, CUtensorMapFloatOOBfill);

extern "C" void kernel_launch(void* const* d_in, const int* in_sizes, int n_in,
                              void* d_out, int out_size) {
    const float* topview = (const float*)d_in[0];
    const float* search  = (const float*)d_in[1];
    const float* w1      = (const float*)d_in[2];
    const float* b1      = (const float*)d_in[3];
    const float* w2      = (const float*)d_in[4];
    const float* b2      = (const float*)d_in[5];
    float* out = (float*)d_out;

    void* fn = nullptr;
    cudaDriverEntryPointQueryResult qr;
#if CUDART_VERSION >= 12050
    cudaGetDriverEntryPointByVersion("cuTensorMapEncodeTiled", &fn, 12000,
                                     cudaEnableDefault, &qr);
#else
    cudaGetDriverEntryPoint("cuTensorMapEncodeTiled", &fn, cudaEnableDefault, &qr);
#endif
    PFN_encode_t encode = (PFN_encode_t)fn;

    CUtensorMap tmB;
    {
        cuuint64_t dims[2]    = {NCLS, KDIM};
        cuuint64_t strides[1] = {(cuuint64_t)NCLS * sizeof(float)};
        cuuint32_t box[2]     = {32, 32};
        cuuint32_t es[2]      = {1, 1};
        encode(&tmB, CU_TENSOR_MAP_DATA_TYPE_FLOAT32, 2, (void*)w2, dims, strides, box, es,
               CU_TENSOR_MAP_INTERLEAVE_NONE, CU_TENSOR_MAP_SWIZZLE_128B,
               CU_TENSOR_MAP_L2_PROMOTION_L2_128B, CU_TENSOR_MAP_FLOAT_OOB_FILL_NONE);
    }

    cudaFuncSetAttribute(k_gemm, cudaFuncAttributeMaxDynamicSharedMemorySize, SMEM_DYN);

    k_tv<<<BATCH, 48>>>(topview);                                   // pos 0
    k_coords2<<<16, 256>>>(w1, b1);                                 // pos 1
    k_gather<<<BATCH * (NPTS / GPTS), 256>>>(search);               // pos 2
    k_gemm<<<dim3(4, KSPLITS), 256, SMEM_DYN>>>(tmB);               // pos 3 (profiled)
    k_reduce1<<<dim3((BATCH * NCLS + 255) / 256, RGROUPS), 256>>>();// pos 4
    k_reduce2<<<(BATCH * NCLS + 255) / 256, 256>>>(out, b2);        // pos 5
}

// round 16
// speedup vs baseline: 1.3316x; 1.3316x over previous
#include <cuda_runtime.h>
#include <cuda.h>
#include <cuda_fp16.h>
#include <cstdint>
#include <math.h>

#define BATCH 64
#define NPTS 2048
#define KDIM 98304            // 2048*48
#define NCLS 1000
#define NPAD 1024
#define KSPLITS 64
#define KSP (KDIM / KSPLITS)  // 1536
#define KB 32                 // K per stage
#define STAGES_PER_CTA (KSP / KB)  // 48
#define TN 256
#define NSTAGES 3
#define RGROUPS 4
#define SPG (KSPLITS / RGROUPS)   // 16

#define B_SLAB 4096                          // 32 k-rows x 128B (fp32, SW128)
#define B_BYTES (8 * B_SLAB)                 // 32768
#define A_SLOT 1056                          // 64 rows x 16B + 32B pad
#define A_BYTES (4 * A_SLOT)                 // 4224
#define STAGE_BYTES 37888                    // 37*1024
#define SMEM_DYN (NSTAGES * STAGE_BYTES + 1024)   // 114688 -> 2 CTAs/SM

// ------------------------- device scratch -------------------------
__device__ float g_tv[BATCH * 48];
__device__ float g_xy[BATCH * NPTS * 2];
__device__ __align__(16) __half g_Ph[(size_t)BATCH * KDIM];  // fp16, k-permuted
__device__ float g_part[(size_t)KSPLITS * BATCH * NPAD];     // 16 MB
__device__ float g_part2[(size_t)RGROUPS * BATCH * NPAD];    // 1 MB

// ------------------------- helpers -------------------------
__device__ __forceinline__ uint32_t smem_u32(const void* p) {
    uint32_t a;
    asm("{ .reg .u64 t; cvta.to.shared.u64 t, %1; cvt.u32.u64 %0, t; }" : "=r"(a) : "l"(p));
    return a;
}
__device__ __forceinline__ void cp_async16(uint32_t dst, const void* src) {
    asm volatile("cp.async.cg.shared.global [%0], [%1], 16;" :: "r"(dst), "l"(src) : "memory");
}
__device__ __forceinline__ void cp_commit() { asm volatile("cp.async.commit_group;" ::: "memory"); }
__device__ __forceinline__ void cp_wait2()  { asm volatile("cp.async.wait_group 2;" ::: "memory"); }
#define MBAR_INIT(addr, cnt) \
    asm volatile("mbarrier.init.shared.b64 [%0], %1;" :: "r"(addr), "r"(cnt) : "memory")
#define MBAR_EXPECT_TX(addr, bytes) \
    asm volatile("mbarrier.arrive.expect_tx.shared.b64 _, [%0], %1;" :: "r"(addr), "r"(bytes) : "memory")
#define MBAR_WAIT(addr, parity) do { \
    uint32_t _m = (addr), _p = (parity), _d; \
    asm volatile("{\n\t.reg .pred p;\n\tmbarrier.try_wait.parity.acquire.cta.shared::cta.b64 p, [%1], %2;\n\tselp.b32 %0,1,0,p;\n\t}" \
        : "=r"(_d) : "r"(_m), "r"(_p) : "memory"); \
    if (!_d) { \
        asm volatile("{\n\t.reg .pred P1;\n\tWL_%=:\n\tmbarrier.try_wait.parity.acquire.cta.shared::cta.b64 P1, [%0], %1, 0x989680;\n\t@P1 bra.uni WD_%=;\n\tbra.uni WL_%=;\n\tWD_%=:\n\t}" \
            :: "r"(_m), "r"(_p) : "memory"); \
    } \
} while (0)
#define TMA_LOAD_2D(smem, map, cx, cy, mbar) \
    asm volatile("cp.async.bulk.tensor.2d.shared::cta.global.tile.mbarrier::complete_tx::bytes [%0], [%1, {%2, %3}], [%4];" \
        :: "r"(smem), "l"(map), "r"(cx), "r"(cy), "r"(mbar) : "memory")

__device__ __forceinline__ uint32_t pack_f16x2(float lo, float hi) {
    uint32_t r;
    asm("cvt.rn.f16x2.f32 %0, %1, %2;" : "=r"(r) : "f"(hi), "f"(lo));
    return r;
}
__device__ __forceinline__ void mma_f16(float* c, uint32_t a0, uint32_t a1, uint32_t a2,
                                        uint32_t a3, uint32_t b0, uint32_t b1) {
    asm volatile(
        "mma.sync.aligned.m16n8k16.row.col.f32.f16.f16.f32 "
        "{%0,%1,%2,%3}, {%4,%5,%6,%7}, {%8,%9}, {%0,%1,%2,%3};"
        : "+f"(c[0]), "+f"(c[1]), "+f"(c[2]), "+f"(c[3])
        : "r"(a0), "r"(a1), "r"(a2), "r"(a3), "r"(b0), "r"(b1));
}

// ---------------------------------------------------------------------------
// Kernel 1a: tv resize. 64 blocks x 48 threads.
// ---------------------------------------------------------------------------
__global__ void k_tv(const float* __restrict__ tv_img) {
    int b = blockIdx.x, d = threadIdx.x;
    int c = d / 16, rem = d % 16, i = rem / 4, j = rem % 4;
    const float* base = tv_img + ((size_t)(b * 3 + c)) * 64 * 64;
    int r0 = 16 * i + 7, c0 = 16 * j + 7;
    g_tv[b * 48 + d] = 0.25f * (base[r0 * 64 + c0] + base[r0 * 64 + c0 + 1] +
                                base[(r0 + 1) * 64 + c0] + base[(r0 + 1) * 64 + c0 + 1]);
}

// ---------------------------------------------------------------------------
// Kernel 1b: coords. 16 CTAs x 256 thr.
// ---------------------------------------------------------------------------
__global__ void __launch_bounds__(256) k_coords2(const float* __restrict__ w1,
                                                 const float* __restrict__ b1) {
    __shared__ float tv_s[BATCH * 48];
    int tid = threadIdx.x;
    int m = blockIdx.x * 256 + tid;
#pragma unroll
    for (int i = 0; i < 12; i++)
        tv_s[tid + i * 256] = g_tv[tid + i * 256];
    __syncthreads();

    float wcol[48];
#pragma unroll
    for (int d = 0; d < 48; d++) wcol[d] = w1[d * 4096 + m];
    float bias = b1[m];
    int p = m >> 1, q = m & 1;

    for (int b = 0; b < BATCH; b++) {
        const float* tvb = &tv_s[b * 48];
        float acc = bias;
#pragma unroll
        for (int d = 0; d < 48; d++) acc += wcol[d] * tvb[d];
        float s = 1.0f / (1.0f + expf(-acc));
        g_xy[(b * NPTS + p) * 2 + q] = s * 1019.0f + 2.0f;
    }
}

// ---------------------------------------------------------------------------
// Kernel 2: gather, division-free, SMEM-staged output (coalesced float4 STG).
// ---------------------------------------------------------------------------
#define GPTS 16
__global__ void __launch_bounds__(256) k_gather(const float* __restrict__ img) {
    __shared__ float px[GPTS][5][16];
    __shared__ float sfx[GPTS], sfy[GPTS];
    __shared__ int   sbase[GPTS];
    __shared__ __align__(16) __half sh_out[GPTS * 48];

    const int tid = threadIdx.x;
    const int g = tid >> 4;
    const int f = tid & 15;
    const int b  = blockIdx.x >> 7;
    const int p0 = (blockIdx.x & 127) << 4;

    if (tid < GPTS) {
        int p = p0 + tid;
        float2 xy = *(const float2*)&g_xy[(b * NPTS + p) * 2];
        float x0 = floorf(xy.x), y0 = floorf(xy.y);
        sfx[tid] = xy.x - x0;
        sfy[tid] = xy.y - y0;
        sbase[tid] = (((int)x0 - 2) << 10) * 3 + ((int)y0 - 2) * 3;
    }
    __syncthreads();

    const float* ib = img + (size_t)b * (1024u * 1024u * 3u);
    if (f < 15) {
        const float* src = ib + sbase[g] + f;
#pragma unroll
        for (int row = 0; row < 5; row++)
            px[g][row][f] = src[row * 3072];
    }
    __syncthreads();

    const int i = f >> 2, j = f & 3;
    float fx = sfx[g], fy = sfy[g];
    float w00 = (1.0f - fx) * (1.0f - fy);
    float w01 = (1.0f - fx) * fy;
    float w10 = fx * (1.0f - fy);
    float w11 = fx * fy;

    const float* r0 = &px[g][i][j * 3];
    const float* r1 = &px[g][i + 1][j * 3];

    int kloc = g * 48 + f * 3;
#pragma unroll
    for (int ch = 0; ch < 3; ch++) {
        float v = r0[ch] * w00 + r0[ch + 3] * w01 + r1[ch] * w10 + r1[ch + 3] * w11;
        int k = kloc + ch;
        int off = k & 31;
        int r = off & 15, kb = off >> 4;
        int t = (r >> 1) & 3, pair = r >> 3, elem = r & 1;
        int pos = (t << 3) | (kb << 2) | (pair << 1) | elem;
        sh_out[(k & ~31) | pos] = __float2half_rn(v);
    }
    __syncthreads();

    if (tid < 96) {
        float4 v4 = *(const float4*)&sh_out[tid * 8];
        *(float4*)&g_Ph[(size_t)b * KDIM + p0 * 48 + tid * 8] = v4;
    }
}

// ---------------------------------------------------------------------------
// Kernel 3: fp16 mma.sync m16n8k16 split-K GEMM (EXACT R13 loop:
// issue-before-wait lag-2, cp_wait2, two syncs per stage).
// TN=256, 2 CTAs/SM, grid (4, 64) = 256 CTAs single wave.
// ---------------------------------------------------------------------------
__global__ void __launch_bounds__(256, 2) k_gemm(const __grid_constant__ CUtensorMap tmB) {
    extern __shared__ __align__(16) char smem_raw[];
    __shared__ __align__(16) uint64_t mbar[NSTAGES];

    const int tid = threadIdx.x;
    const int wid = tid >> 5;
    const int lane = tid & 31;
    const int n0 = blockIdx.x * TN;
    const int ksplit = blockIdx.y;
    const int k0 = ksplit * KSP;
    const int g  = lane >> 2;
    const int t  = lane & 3;

    const uint32_t sbase = (smem_u32(smem_raw) + 1023u) & ~1023u;
    const uint32_t mb = smem_u32(mbar);

    if (tid == 0) {
#pragma unroll
        for (int s = 0; s < NSTAGES; s++) MBAR_INIT(mb + s * 8, 1);
    }
    __syncthreads();

    auto issue_A = [&](int slot, int kofs) {
        uint32_t st = sbase + slot * STAGE_BYTES + B_BYTES;
        int row = tid & 63, c = tid >> 6;
        cp_async16(st + c * A_SLOT + row * 16,
                   &g_Ph[(size_t)row * KDIM + kofs + c * 8]);
        cp_commit();
    };
    auto issue_B = [&](int slot, int kofs) {
        if (tid == 0) {
            uint32_t full = mb + slot * 8;
            uint32_t bdst = sbase + slot * STAGE_BYTES;
            MBAR_EXPECT_TX(full, B_BYTES);
#pragma unroll
            for (int j = 0; j < 8; j++)
                TMA_LOAD_2D(bdst + j * B_SLAB, &tmB, n0 + 32 * j, kofs, full);
        }
    };

    // prologue: stages 0 and 1
    issue_B(0, k0);           issue_A(0, k0);
    issue_B(1, k0 + KB);      issue_A(1, k0 + KB);

    float acc[16][4];
#pragma unroll
    for (int j = 0; j < 16; j++)
#pragma unroll
        for (int r = 0; r < 4; r++) acc[j][r] = 0.0f;

    uint32_t col0[4], col1[4];
#pragma unroll
    for (int nt = 0; nt < 4; nt++) {
        uint32_t n = nt * 8 + g;
        uint32_t chunk = n >> 2, e = (n & 3) * 4;
        col0[nt] = ((chunk ^ (uint32_t)(2 * t)) << 4) + e;
        col1[nt] = ((chunk ^ (uint32_t)(2 * t + 1)) << 4) + e;
    }

    int slot = 0, phase = 0;        // consumer cursor
    int pslot = 2;                  // producer slot for stage s+2
    for (int s = 0; s < STAGES_PER_CTA; s++) {
        int sn = s + 2;
        if (sn < STAGES_PER_CTA) {         // issue BEFORE wait: 2 stages in flight
            issue_B(pslot, k0 + sn * KB);
            issue_A(pslot, k0 + sn * KB);
        } else cp_commit();                // keep wait_group accounting aligned
        if (++pslot == NSTAGES) pslot = 0;

        cp_wait2();                        // A(s) complete (<=2 groups outstanding)
        MBAR_WAIT(mb + slot * 8, phase);   // B(s) complete
        __syncthreads();

        uint32_t st = sbase + slot * STAGE_BYTES;
        uint32_t abase = st + B_BYTES + t * A_SLOT;
        uint32_t bslab = st + wid * B_SLAB;

        uint4 av[8];
#pragma unroll
        for (int jr = 0; jr < 8; jr++) {
            asm volatile("ld.shared.v4.u32 {%0,%1,%2,%3}, [%4];"
                : "=r"(av[jr].x), "=r"(av[jr].y), "=r"(av[jr].z), "=r"(av[jr].w)
                : "r"(abase + (jr * 8 + g) * 16));
        }

#pragma unroll
        for (int kb = 0; kb < 2; kb++) {
            uint32_t rb0 = bslab + (kb * 16 + 2 * t) * 128;
            uint32_t rb1 = rb0 + 128;
#pragma unroll
            for (int nt = 0; nt < 4; nt++) {
                float v00, v01, v10, v11;
                asm volatile("ld.shared.f32 %0, [%1];" : "=f"(v00) : "r"(rb0 + col0[nt]));
                asm volatile("ld.shared.f32 %0, [%1];" : "=f"(v01) : "r"(rb1 + col1[nt]));
                asm volatile("ld.shared.f32 %0, [%1];" : "=f"(v10) : "r"(rb0 + 1024 + col0[nt]));
                asm volatile("ld.shared.f32 %0, [%1];" : "=f"(v11) : "r"(rb1 + 1024 + col1[nt]));
                uint32_t b0 = pack_f16x2(v00, v01);
                uint32_t b1 = pack_f16x2(v10, v11);
#pragma unroll
                for (int mt = 0; mt < 4; mt++) {
                    uint32_t a0 = kb ? av[2 * mt].z     : av[2 * mt].x;
                    uint32_t a2 = kb ? av[2 * mt].w     : av[2 * mt].y;
                    uint32_t a1 = kb ? av[2 * mt + 1].z : av[2 * mt + 1].x;
                    uint32_t a3 = kb ? av[2 * mt + 1].w : av[2 * mt + 1].y;
                    mma_f16(acc[mt * 4 + nt], a0, a1, a2, a3, b0, b1);
                }
            }
        }
        __syncthreads();
        if (++slot == NSTAGES) { slot = 0; phase ^= 1; }
    }

    float* base = &g_part[(size_t)ksplit * BATCH * NPAD];
#pragma unroll
    for (int mt = 0; mt < 4; mt++) {
#pragma unroll
        for (int nt = 0; nt < 4; nt++) {
            int m = mt * 16 + g;
            int n = n0 + wid * 32 + nt * 8 + 2 * t;
            float* a = acc[mt * 4 + nt];
            *(float2*)&base[(size_t)m * NPAD + n] = make_float2(a[0], a[1]);
            *(float2*)&base[(size_t)(m + 8) * NPAD + n] = make_float2(a[2], a[3]);
        }
    }
}

// ---------------------------------------------------------------------------
// Kernel 4a: reduce phase 1 — each (output, group) sums SPG splits
// ---------------------------------------------------------------------------
__global__ void k_reduce1() {
    int idx = blockIdx.x * blockDim.x + threadIdx.x;
    if (idx >= BATCH * NCLS) return;
    int grp = blockIdx.y;
    int b = idx / NCLS, n = idx % NCLS;
    float acc = 0.0f;
#pragma unroll
    for (int s = 0; s < SPG; s++)
        acc += g_part[((size_t)(grp * SPG + s) * BATCH + b) * NPAD + n];
    g_part2[((size_t)grp * BATCH + b) * NPAD + n] = acc;
}

// ---------------------------------------------------------------------------
// Kernel 4b: reduce phase 2 — sum RGROUPS + bias -> out
// ---------------------------------------------------------------------------
__global__ void k_reduce2(float* __restrict__ out, const float* __restrict__ b2) {
    int idx = blockIdx.x * blockDim.x + threadIdx.x;
    if (idx >= BATCH * NCLS) return;
    int b = idx / NCLS, n = idx % NCLS;
    float acc = b2[n];
#pragma unroll
    for (int g = 0; g < RGROUPS; g++)
        acc += g_part2[((size_t)g * BATCH + b) * NPAD + n];
    out[idx] = acc;
}

// ---------------------------------------------------------------------------
typedef CUresult (*PFN_encode_t)(CUtensorMap*, CUtensorMapDataType, cuuint32_t, void*,
                                 const cuuint64_t*, const cuuint64_t*, const cuuint32_t*,
                                 const cuuint32_t*, CUtensorMapInterleave, CUtensorMapSwizzle,
                                 CUtensorMapL2promotion, CUtensorMapFloatOOBfill);

extern "C" void kernel_launch(void* const* d_in, const int* in_sizes, int n_in,
                              void* d_out, int out_size) {
    const float* topview = (const float*)d_in[0];
    const float* search  = (const float*)d_in[1];
    const float* w1      = (const float*)d_in[2];
    const float* b1      = (const float*)d_in[3];
    const float* w2      = (const float*)d_in[4];
    const float* b2      = (const float*)d_in[5];
    float* out = (float*)d_out;

    void* fn = nullptr;
    cudaDriverEntryPointQueryResult qr;
#if CUDART_VERSION >= 12050
    cudaGetDriverEntryPointByVersion("cuTensorMapEncodeTiled", &fn, 12000,
                                     cudaEnableDefault, &qr);
#else
    cudaGetDriverEntryPoint("cuTensorMapEncodeTiled", &fn, cudaEnableDefault, &qr);
#endif
    PFN_encode_t encode = (PFN_encode_t)fn;

    CUtensorMap tmB;
    {
        cuuint64_t dims[2]    = {NCLS, KDIM};
        cuuint64_t strides[1] = {(cuuint64_t)NCLS * sizeof(float)};
        cuuint32_t box[2]     = {32, 32};
        cuuint32_t es[2]      = {1, 1};
        encode(&tmB, CU_TENSOR_MAP_DATA_TYPE_FLOAT32, 2, (void*)w2, dims, strides, box, es,
               CU_TENSOR_MAP_INTERLEAVE_NONE, CU_TENSOR_MAP_SWIZZLE_128B,
               CU_TENSOR_MAP_L2_PROMOTION_L2_128B, CU_TENSOR_MAP_FLOAT_OOB_FILL_NONE);
    }

    cudaFuncSetAttribute(k_gemm, cudaFuncAttributeMaxDynamicSharedMemorySize, SMEM_DYN);

    k_tv<<<BATCH, 48>>>(topview);                                   // pos 0
    k_coords2<<<16, 256>>>(w1, b1);                                 // pos 1
    k_gather<<<BATCH * (NPTS / GPTS), 256>>>(search);               // pos 2
    k_gemm<<<dim3(4, KSPLITS), 256, SMEM_DYN>>>(tmB);               // pos 3 (profiled)
    k_reduce1<<<dim3((BATCH * NCLS + 255) / 256, RGROUPS), 256>>>();// pos 4
    k_reduce2<<<(BATCH * NCLS + 255) / 256, 256>>>(out, b2);        // pos 5
}